// round 13
// baseline (speedup 1.0000x reference)
#include <cuda_runtime.h>
#include <cstdint>

#define NROI 6144
#define NCLS 20
#define KSEL 615            // ceil(0.1 * 6144)
#define CSORT 1024
#define AW 20               // ceil(KSEL/32)
#define IOU_TH 0.25f
#define LMAX 16384
#define LCACHE 2048
#define NFB 48              // final blocks (128 ROIs each)
#define KCAP 128            // staged kept-list capacity per class
#define RPB 308             // transpose rows per class block (20*308 >= 6144)

// ---- scratch (device globals; no allocations allowed) ----
__device__ float g_predsT[NCLS * NROI];      // preds[c][i], coalesced per class
__device__ int g_list[LMAX];                 // merged kept list (dups OK)
__device__ unsigned long long g_lv[LMAX];    // packed (prob_bits<<32)|(NCLS-c)
__device__ int g_cnt;                        // reset by final kernel for replay
__device__ unsigned int g_sync;              // monotonic ticket barrier (never reset)

__device__ __forceinline__ void upd(float& mv, int& mj, float v, int j) {
    if (v > mv || (v == mv && j < mj)) { mv = v; mj = j; }
}

// ============================================================
// Kernel 1: 20 blocks. Phase 0: cooperative transpose of
// preds = pc[:,1:]*pd[:,1:] into g_predsT (smem-staged, fully
// coalesced both sides) + monotonic ticket barrier.
// Phase 1: per-class radix select -> sort -> NMS -> publish.
// ============================================================
__global__ void __launch_bounds__(1024, 1)
class_nms_kernel(const float4* __restrict__ pc4,
                 const float4* __restrict__ pd4,
                 const int* __restrict__ labels,
                 const float* __restrict__ iou) {
    extern __shared__ float sp[];                       // RPB*21 floats = 25.9KB
    __shared__ unsigned long long cand[CSORT];          // 8KB
    __shared__ unsigned int sh_hist[256];
    __shared__ unsigned int sh_wsum[8];
    __shared__ unsigned int sh_prefix, sh_k;
    __shared__ int sh_nc, sh_next, sh_kcnt, sh_base;
    __shared__ unsigned int am[AW];
    __shared__ int s_kidx[KCAP];
    __shared__ unsigned long long s_klv[KCAP];

    const int c = blockIdx.x;
    const int t = threadIdx.x;

    // ---------- Phase 0: cooperative transpose ----------
    {
        const int rs = c * RPB;
        const int re = min(NROI, rs + RPB);
        const int nrows = re - rs;
        const int fs = rs * 21, fe = re * 21;
        const int q0 = fs >> 2, q1 = (fe + 3) >> 2;
        for (int q = q0 + t; q < q1; q += 1024) {
            float4 a = pc4[q];
            float4 d = pd4[q];
            int k = 4 * q;
            if (k >= fs && k + 3 < fe) {                // fast path: fully inside
                sp[k - fs]     = a.x * d.x;
                sp[k - fs + 1] = a.y * d.y;
                sp[k - fs + 2] = a.z * d.z;
                sp[k - fs + 3] = a.w * d.w;
            } else {
                if (k   >= fs && k   < fe) sp[k - fs]     = a.x * d.x;
                if (k+1 >= fs && k+1 < fe) sp[k+1 - fs]   = a.y * d.y;
                if (k+2 >= fs && k+2 < fe) sp[k+2 - fs]   = a.z * d.z;
                if (k+3 >= fs && k+3 < fe) sp[k+3 - fs]   = a.w * d.w;
            }
        }
        __syncthreads();
        for (int e = t; e < nrows * NCLS; e += 1024) {
            int cc = e / nrows;
            int r  = e - cc * nrows;                    // consecutive e -> consecutive r
            g_predsT[cc * NROI + rs + r] = sp[r * 21 + cc + 1];
        }
        __syncthreads();
        // monotonic ticket barrier across the 20 blocks (replay-safe)
        if (t == 0) {
            __threadfence();
            unsigned int old = atomicAdd(&g_sync, 1u);
            unsigned int target = (old / (unsigned)NCLS) * (unsigned)NCLS + (unsigned)NCLS;
            while (*((volatile unsigned int*)&g_sync) < target) { }
        }
        __syncthreads();
        __threadfence();
    }

    if (labels[c] == 0) return;

    // ---------- Phase 1: per-class top-K + NMS ----------
    // coalesced inverted keys (ascending == prob descending)
    unsigned int key[6];
    #pragma unroll
    for (int r = 0; r < 6; ++r)
        key[r] = ~__float_as_uint(g_predsT[c * NROI + r * 1024 + t]);
    if (t == 0) { sh_prefix = 0; sh_k = KSEL; }
    __syncthreads();

    // ---- 4-pass MSB radix select ----
    for (int shift = 24; shift >= 0; shift -= 8) {
        if (t < 256) sh_hist[t] = 0;
        __syncthreads();
        const unsigned int prefix = sh_prefix;
        const unsigned int kcur   = sh_k;
        const unsigned int pmask  = (shift == 24) ? 0u : (0xFFFFFFFFu << (shift + 8));
        #pragma unroll
        for (int r = 0; r < 6; ++r) {
            bool active = ((key[r] & pmask) == prefix);
            unsigned int act = __ballot_sync(0xFFFFFFFFu, active);
            if (active) {
                unsigned int bin = (key[r] >> shift) & 0xFF;
                unsigned int peers = __match_any_sync(act, bin);
                if ((t & 31) == __ffs(peers) - 1)
                    atomicAdd(&sh_hist[bin], (unsigned int)__popc(peers));
            }
        }
        __syncthreads();
        unsigned int x = 0, hval = 0;
        if (t < 256) {
            hval = sh_hist[t];
            x = hval;
            #pragma unroll
            for (int off = 1; off < 32; off <<= 1) {
                unsigned int y = __shfl_up_sync(0xFFFFFFFFu, x, off);
                if ((t & 31) >= off) x += y;
            }
            if ((t & 31) == 31) sh_wsum[t >> 5] = x;
        }
        __syncthreads();
        if (t < 8) {
            unsigned int w = sh_wsum[t];
            #pragma unroll
            for (int off = 1; off < 8; off <<= 1) {
                unsigned int y = __shfl_up_sync(0xFFu, w, off);
                if (t >= off) w += y;
            }
            sh_wsum[t] = w;
        }
        __syncthreads();
        if (t < 256) {
            unsigned int incl = x + ((t >= 32) ? sh_wsum[(t >> 5) - 1] : 0u);
            unsigned int excl = incl - hval;
            if (incl >= kcur && excl < kcur) {
                sh_prefix = prefix | ((unsigned int)t << shift);
                sh_k = kcur - excl;
            }
        }
        __syncthreads();
    }
    const unsigned int thr = sh_prefix;

    // ---- warp-aggregated compaction (key <= thr) ----
    if (t == 0) sh_nc = 0;
    __syncthreads();
    #pragma unroll
    for (int r = 0; r < 6; ++r) {
        bool sel = (key[r] <= thr);
        unsigned int m = __ballot_sync(0xFFFFFFFFu, sel);
        if (sel) {
            int lane = t & 31;
            int base = 0;
            if (__ffs(m) - 1 == lane)
                base = atomicAdd(&sh_nc, __popc(m));
            base = __shfl_sync(m, base, __ffs(m) - 1);
            int pos = base + __popc(m & ((1u << lane) - 1));
            if (pos < CSORT)
                cand[pos] = ((unsigned long long)key[r] << 32) |
                            (unsigned int)(r * 1024 + t);
        }
    }
    __syncthreads();
    const int nc = sh_nc;
    if (t >= nc && t < CSORT) cand[t] = 0xFFFFFFFFFFFFFFFFull;
    __syncthreads();

    // ---- bitonic sort 1024 u64 (shfl j<=16, smem j>=32) ----
    {
        unsigned long long v = cand[t];
        #pragma unroll
        for (unsigned int k = 2; k <= 32; k <<= 1) {
            bool asc = ((t & k) == 0);
            #pragma unroll
            for (unsigned int j = k >> 1; j >= 1; j >>= 1) {
                unsigned long long o = __shfl_xor_sync(0xFFFFFFFFu, v, j);
                bool keepmin = (((t & j) == 0) == asc);
                v = (keepmin == (v <= o)) ? v : o;
            }
        }
        cand[t] = v;
    }
    __syncthreads();
    for (unsigned int k = 64; k <= CSORT; k <<= 1) {
        for (unsigned int j = k >> 1; j >= 32; j >>= 1) {
            unsigned int i = t, ixj = i ^ j;
            if (ixj > i) {
                unsigned long long a = cand[i], b = cand[ixj];
                bool asc = ((i & k) == 0);
                if ((a > b) == asc) { cand[i] = b; cand[ixj] = a; }
            }
            __syncthreads();
        }
        {
            unsigned long long v = cand[t];
            bool asc = ((t & k) == 0);
            #pragma unroll
            for (unsigned int j = 16; j >= 1; j >>= 1) {
                unsigned long long o = __shfl_xor_sync(0xFFFFFFFFu, v, j);
                bool keepmin = (((t & j) == 0) == asc);
                v = (keepmin == (v <= o)) ? v : o;
            }
            cand[t] = v;
        }
        __syncthreads();
    }

    // ---- greedy NMS; kept list staged in smem ----
    for (int w = t; w < AW; w += 1024) am[w] = 0xFFFFFFFFu;
    if (t == 0) {
        am[AW - 1] = (1u << (KSEL - 32 * (AW - 1))) - 1;
        sh_next = 0;
        sh_kcnt = 0;
    }
    __syncthreads();

    while (true) {
        const int i = sh_next;
        if (i >= KSEL) break;
        const unsigned long long ci = cand[i];
        const int oi = (unsigned int)ci;
        if (t == 0) {
            int kpos = sh_kcnt;
            if (kpos < KCAP) {
                s_kidx[kpos] = oi;
                s_klv[kpos] = ((unsigned long long)(~(unsigned int)(ci >> 32)) << 32) |
                              (unsigned long long)(unsigned int)(NCLS - c);
            }
            sh_kcnt = kpos + 1;
        }
        const int j = i + 1 + t;
        if (j < KSEL && ((am[j >> 5] >> (j & 31)) & 1u)) {
            const int oj = (unsigned int)cand[j];
            float v = iou[(size_t)oi * NROI + oj];
            if (v >= IOU_TH) atomicAnd(&am[j >> 5], ~(1u << (j & 31)));
        }
        __syncthreads();
        if (t == 0) {
            int nx = KSEL;
            int start = i + 1;
            int w = start >> 5;
            unsigned int m = (w < AW) ? (am[w] & (0xFFFFFFFFu << (start & 31))) : 0u;
            while (true) {
                if (m) { nx = (w << 5) + __ffs(m) - 1; break; }
                if (++w >= AW) break;
                m = am[w];
            }
            sh_next = nx;
        }
        __syncthreads();
    }

    // ---- bulk publish ----
    const int kcnt = min(sh_kcnt, KCAP);
    if (t == 0) sh_base = atomicAdd(&g_cnt, kcnt);
    __syncthreads();
    if (t < kcnt) {
        g_list[sh_base + t] = s_kidx[t];
        g_lv[sh_base + t]   = s_klv[t];
    }
}

// ============================================================
// Kernel 2: fused partial-max + class resolution + emit.
// 48 blocks x 1024: 128 ROIs/block, 8 chunks x 8-way ILP.
// ============================================================
__global__ void __launch_bounds__(1024, 1)
fused_final_kernel(const float* __restrict__ iou, float* __restrict__ out) {
    extern __shared__ unsigned long long dyn[];
    unsigned long long* s_cw   = dyn;                   // NROI u64 = 48KB
    unsigned long long* s_part = dyn + NROI;            // 1024 u64 = 8KB
    int*   s_list = (int*)(s_part + 1024);              // LCACHE ints
    int*   s_lab  = s_list + LCACHE;
    float* s_v    = (float*)(s_lab + 128);
    float* s_w    = s_v + 128;

    const int t  = threadIdx.x;
    const int bi = blockIdx.x;
    const int il = t & 127;
    const int ch = t >> 7;                              // 0..7
    const int i  = bi * 128 + il;

    const int G = g_cnt;

    for (int e = t; e < NROI; e += 1024) s_cw[e] = 0ull;
    __syncthreads();
    for (int e = t; e < G; e += 1024) {
        int oi = g_list[e];
        if (e < LCACHE) s_list[e] = oi;
        atomicMax(&s_cw[oi], g_lv[e]);
    }
    __syncthreads();

    const int len = (G + 7) >> 3;
    const int g0 = ch * len;
    const int g1 = min(G, g0 + len);

    unsigned long long pkey = 0ull;
    if (g0 < g1) {
        float mv[8]; int mj[8];
        #pragma unroll
        for (int r = 0; r < 8; ++r) { mv[r] = -1.0f; mj[r] = 0; }
        int g = g0;
        for (; g + 8 <= g1; g += 8) {
            #pragma unroll
            for (int r = 0; r < 8; ++r) {
                int j = s_list[g + r];
                upd(mv[r], mj[r], iou[(size_t)j * NROI + i], j);
            }
        }
        #pragma unroll 8
        for (; g < g1; ++g) {
            int j = s_list[g];
            upd(mv[0], mj[0], iou[(size_t)j * NROI + i], j);
        }
        #pragma unroll
        for (int r = 4; r >= 1; r >>= 1)
            #pragma unroll
            for (int r2 = 0; r2 < 8; ++r2)
                if (r2 < r) upd(mv[r2], mj[r2], mv[r2 + r], mj[r2 + r]);
        pkey = ((unsigned long long)__float_as_uint(mv[0]) << 32) |
               (unsigned long long)(unsigned int)(NROI - mj[0]);
    }
    s_part[t] = pkey;
    __syncthreads();

    if (t < 128) {
        unsigned long long best = s_part[t];
        #pragma unroll
        for (int r = 1; r < 8; ++r) {
            unsigned long long b2 = s_part[t + r * 128];
            if (b2 > best) best = b2;
        }
        const float maxv = __uint_as_float((unsigned int)(best >> 32));
        const int   maxj = NROI - (int)(unsigned int)(best & 0xFFFFFFFFull);

        const unsigned long long cw = s_cw[maxj];
        const int   cls = (int)(NCLS + 1) - (int)(unsigned int)(cw & 0xFFFFFFFFull);
        const float lw  = __uint_as_float((unsigned int)(cw >> 32));

        const bool ignore = (maxv == 0.0f);
        const bool bg     = (maxv < IOU_TH) && !ignore;
        s_lab[t] = ignore ? -1 : (bg ? 0 : cls);
        s_v[t]   = maxv;
        s_w[t]   = ignore ? 0.0f : lw;
    }
    __syncthreads();

    const size_t base = (size_t)bi * 128 * (NCLS + 1);
    for (int e = t; e < 128 * (NCLS + 1); e += 1024) {
        int row = e / (NCLS + 1);
        int k   = e - row * (NCLS + 1);
        out[base + e] = (k == s_lab[row]) ? 1.0f : 0.0f;
    }
    if (t < 128) {
        out[(size_t)NROI * (NCLS + 1) + i]        = s_v[t];
        out[(size_t)NROI * (NCLS + 1) + NROI + i] = s_w[t];
    }

    // reset for next replay (wave-1 co-resident blocks already read g_cnt)
    if (bi == 0 && t == 0) g_cnt = 0;
}

extern "C" void kernel_launch(void* const* d_in, const int* in_sizes, int n_in,
                              void* d_out, int out_size) {
    const float* pc     = (const float*)d_in[0];
    const float* pd     = (const float*)d_in[1];
    // d_in[2] = rois (unused)
    const int*   labels = (const int*)d_in[3];
    const float* iou    = (const float*)d_in[4];
    float* out = (float*)d_out;

    const int dsmem_cls = RPB * 21 * (int)sizeof(float);             // 25.9KB
    const int dsmem_fin = NROI * 8 + 1024 * 8 + LCACHE * 4 + 128 * 12;
    cudaFuncSetAttribute(fused_final_kernel,
                         cudaFuncAttributeMaxDynamicSharedMemorySize, dsmem_fin);

    class_nms_kernel<<<NCLS, 1024, dsmem_cls>>>(
        (const float4*)pc, (const float4*)pd, labels, iou);
    fused_final_kernel<<<NFB, 1024, dsmem_fin>>>(iou, out);
}

// round 14
// speedup vs baseline: 1.1676x; 1.1676x over previous
#include <cuda_runtime.h>
#include <cstdint>

#define NROI 6144
#define NCLS 20
#define KSEL 615            // ceil(0.1 * 6144)
#define CSORT 1024
#define IOU_TH 0.25f
#define LMAX 16384
#define GMAX 2560           // max merged kept entries (20*KCAP)
#define NFB 48              // final blocks (128 ROIs each)
#define KCAP 128            // staged kept-list capacity per class

// ---- scratch (device globals; no allocations allowed) ----
__device__ float g_predsT[NCLS * NROI];      // preds[c][i], coalesced per class
__device__ int g_list[LMAX];                 // merged kept list (dups OK)
__device__ unsigned long long g_lv[LMAX];    // packed (prob_bits<<32)|(NCLS-c)
__device__ int g_cnt;                        // reset by final kernel for replay

__device__ __forceinline__ void upd(float& mv, int& mj, float v, int j) {
    if (v > mv || (v == mv && j < mj)) { mv = v; mj = j; }
}

// block-wide u64 min over 1024 threads (32 warps); 3 barriers
__device__ __forceinline__ unsigned long long
blockMinU64(unsigned long long v, unsigned long long* s_red, int t) {
    #pragma unroll
    for (int o = 16; o; o >>= 1) {
        unsigned long long u = __shfl_xor_sync(0xFFFFFFFFu, v, o);
        v = (u < v) ? u : v;
    }
    if ((t & 31) == 0) s_red[t >> 5] = v;
    __syncthreads();
    if (t < 32) {
        unsigned long long w = s_red[t];
        #pragma unroll
        for (int o = 16; o; o >>= 1) {
            unsigned long long u = __shfl_xor_sync(0xFFFFFFFFu, w, o);
            w = (u < w) ? u : w;
        }
        if (t == 0) s_red[0] = w;
    }
    __syncthreads();
    unsigned long long r = s_red[0];
    __syncthreads();
    return r;
}

// ============================================================
// Kernel 0: coalesced float4 transpose (R12, measured 4.7us)
// ============================================================
__global__ void __launch_bounds__(256)
preds_kernel(const float4* __restrict__ pc4, const float4* __restrict__ pd4) {
    __shared__ float sp[64 * 21];
    const int b  = blockIdx.x;
    const int t  = threadIdx.x;
    const int i0 = b * 64;
    const int base4 = b * 336;

    float4* sp4 = (float4*)sp;
    #pragma unroll
    for (int r = 0; r < 2; ++r) {
        int idx = t + r * 256;
        if (idx < 336) {
            float4 a = pc4[base4 + idx];
            float4 d = pd4[base4 + idx];
            float4 o;
            o.x = a.x * d.x; o.y = a.y * d.y; o.z = a.z * d.z; o.w = a.w * d.w;
            sp4[idx] = o;
        }
    }
    __syncthreads();
    #pragma unroll
    for (int r = 0; r < 5; ++r) {
        int e = t + r * 256;
        int c = e >> 6;
        int i = e & 63;
        g_predsT[c * NROI + i0 + i] = sp[i * 21 + c + 1];
    }
}

// ============================================================
// Kernel 1: one block per class; label==0 classes exit.
//   radix select (exact 615th threshold + within-key rank m)
//   -> compact (unsorted) -> iterated argmin greedy NMS
//   -> bulk publish.
// ============================================================
__global__ void __launch_bounds__(1024, 1)
class_nms_kernel(const int* __restrict__ labels,
                 const float* __restrict__ iou) {
    __shared__ unsigned long long cand[CSORT];          // 8KB
    __shared__ unsigned long long s_red[32];
    __shared__ unsigned int sh_hist[256];
    __shared__ unsigned int sh_wsum[8];
    __shared__ unsigned int sh_prefix, sh_k;
    __shared__ int sh_nc, sh_kc, sh_base;
    __shared__ int s_kidx[KCAP];
    __shared__ unsigned long long s_klv[KCAP];

    const int c = blockIdx.x;
    const int t = threadIdx.x;

    if (labels[c] == 0) return;

    // coalesced inverted keys (ascending == prob descending)
    unsigned int key[6];
    #pragma unroll
    for (int r = 0; r < 6; ++r)
        key[r] = ~__float_as_uint(g_predsT[c * NROI + r * 1024 + t]);
    if (t == 0) { sh_prefix = 0; sh_k = KSEL; }
    __syncthreads();

    // ---- 4-pass MSB radix select (exact threshold) ----
    for (int shift = 24; shift >= 0; shift -= 8) {
        if (t < 256) sh_hist[t] = 0;
        __syncthreads();
        const unsigned int prefix = sh_prefix;
        const unsigned int kcur   = sh_k;
        const unsigned int pmask  = (shift == 24) ? 0u : (0xFFFFFFFFu << (shift + 8));
        #pragma unroll
        for (int r = 0; r < 6; ++r) {
            bool active = ((key[r] & pmask) == prefix);
            unsigned int act = __ballot_sync(0xFFFFFFFFu, active);
            if (active) {
                unsigned int bin = (key[r] >> shift) & 0xFF;
                unsigned int peers = __match_any_sync(act, bin);
                if ((t & 31) == __ffs(peers) - 1)
                    atomicAdd(&sh_hist[bin], (unsigned int)__popc(peers));
            }
        }
        __syncthreads();
        unsigned int x = 0, hval = 0;
        if (t < 256) {
            hval = sh_hist[t];
            x = hval;
            #pragma unroll
            for (int off = 1; off < 32; off <<= 1) {
                unsigned int y = __shfl_up_sync(0xFFFFFFFFu, x, off);
                if ((t & 31) >= off) x += y;
            }
            if ((t & 31) == 31) sh_wsum[t >> 5] = x;
        }
        __syncthreads();
        if (t < 8) {
            unsigned int w = sh_wsum[t];
            #pragma unroll
            for (int off = 1; off < 8; off <<= 1) {
                unsigned int y = __shfl_up_sync(0xFFu, w, off);
                if (t >= off) w += y;
            }
            sh_wsum[t] = w;
        }
        __syncthreads();
        if (t < 256) {
            unsigned int incl = x + ((t >= 32) ? sh_wsum[(t >> 5) - 1] : 0u);
            unsigned int excl = incl - hval;
            if (incl >= kcur && excl < kcur) {
                sh_prefix = prefix | ((unsigned int)t << shift);
                sh_k = kcur - excl;
            }
        }
        __syncthreads();
    }
    const unsigned int thr = sh_prefix;
    const int m = (int)sh_k;                 // rank within the exact-key group

    // ---- warp-aggregated compaction (key <= thr), unsorted ----
    if (t == 0) sh_nc = 0;
    __syncthreads();
    #pragma unroll
    for (int r = 0; r < 6; ++r) {
        bool sel = (key[r] <= thr);
        unsigned int bm = __ballot_sync(0xFFFFFFFFu, sel);
        if (sel) {
            int lane = t & 31;
            int base = 0;
            if (__ffs(bm) - 1 == lane)
                base = atomicAdd(&sh_nc, __popc(bm));
            base = __shfl_sync(bm, base, __ffs(bm) - 1);
            int pos = base + __popc(bm & ((1u << lane) - 1));
            if (pos < CSORT)
                cand[pos] = ((unsigned long long)key[r] << 32) |
                            (unsigned int)(r * 1024 + t);
        }
    }
    __syncthreads();
    const int nc = sh_nc;
    if (t >= nc) cand[t] = 0xFFFFFFFFFFFFFFFFull;
    __syncthreads();

    // per-thread slot
    const unsigned long long myc = cand[t];
    const unsigned int mykey = (unsigned int)(myc >> 32);
    const int myidx = (int)(unsigned int)(myc & 0xFFFFFFFFull);

    // ---- exact participation: key<thr always; ties at thr need the
    //      m smallest indices (m-step min extraction; m is tiny) ----
    unsigned long long tv = (t < nc && mykey == thr)
        ? (unsigned long long)(unsigned int)myidx : 0xFFFFFFFFFFFFFFFFull;
    int idx_thr = -1;
    for (int it = 0; it < m; ++it) {
        unsigned long long mn = blockMinU64(tv, s_red, t);
        idx_thr = (int)(unsigned int)mn;
        if (tv == mn) tv = 0xFFFFFFFFFFFFFFFFull;
    }
    bool alive = (t < nc) &&
                 (mykey < thr || (mykey == thr && myidx <= idx_thr));

    // ---- greedy NMS: iterated extract-min over alive candidates ----
    if (t == 0) sh_kc = 0;
    while (true) {
        unsigned long long v = alive ? myc : 0xFFFFFFFFFFFFFFFFull;
        unsigned long long win = blockMinU64(v, s_red, t);
        if (win == 0xFFFFFFFFFFFFFFFFull) break;
        const int oi = (int)(unsigned int)(win & 0xFFFFFFFFull);
        if (t == 0) {
            int kp = sh_kc;
            if (kp < KCAP) {
                s_kidx[kp] = oi;
                s_klv[kp] = ((unsigned long long)(~(unsigned int)(win >> 32)) << 32) |
                            (unsigned long long)(unsigned int)(NCLS - c);
            }
            sh_kc = kp + 1;
        }
        if (alive) {
            float vio = iou[(size_t)oi * NROI + myidx];
            if (vio >= IOU_TH) alive = false;      // winner self-suppresses (diag=1)
        }
        // blockMinU64 at loop head re-synchronizes before s_red reuse
    }

    // ---- bulk publish ----
    __syncthreads();
    const int kcnt = min(sh_kc, KCAP);
    if (t == 0) sh_base = atomicAdd(&g_cnt, kcnt);
    __syncthreads();
    if (t < kcnt) {
        g_list[sh_base + t] = s_kidx[t];
        g_lv[sh_base + t]   = s_klv[t];
    }
}

// ============================================================
// Kernel 2: fused partial-max + per-thread list-scan resolution.
// 48 blocks x 1024: 128 ROIs/block, 8 chunks x 8-way ILP.
// No class table: scan the G-entry smem list for maxj instead.
// ============================================================
__global__ void __launch_bounds__(1024, 1)
fused_final_kernel(const float* __restrict__ iou, float* __restrict__ out) {
    __shared__ int s_idx[GMAX];                         // 10KB
    __shared__ unsigned long long s_lvl[GMAX];          // 20KB
    __shared__ unsigned long long s_part[1024];         // 8KB
    __shared__ int   s_lab[128];
    __shared__ float s_v[128];
    __shared__ float s_w[128];

    const int t  = threadIdx.x;
    const int bi = blockIdx.x;
    const int il = t & 127;
    const int ch = t >> 7;                              // 0..7
    const int i  = bi * 128 + il;

    const int G = min(g_cnt, GMAX);

    for (int e = t; e < G; e += 1024) {
        s_idx[e] = g_list[e];
        s_lvl[e] = g_lv[e];
    }
    __syncthreads();

    const int len = (G + 7) >> 3;
    const int g0 = ch * len;
    const int g1 = min(G, g0 + len);

    unsigned long long pkey = 0ull;
    if (g0 < g1) {
        float mv[8]; int mj[8];
        #pragma unroll
        for (int r = 0; r < 8; ++r) { mv[r] = -1.0f; mj[r] = 0; }
        int g = g0;
        for (; g + 8 <= g1; g += 8) {
            #pragma unroll
            for (int r = 0; r < 8; ++r) {
                int j = s_idx[g + r];
                upd(mv[r], mj[r], iou[(size_t)j * NROI + i], j);
            }
        }
        #pragma unroll 8
        for (; g < g1; ++g) {
            int j = s_idx[g];
            upd(mv[0], mj[0], iou[(size_t)j * NROI + i], j);
        }
        #pragma unroll
        for (int r = 4; r >= 1; r >>= 1)
            #pragma unroll
            for (int r2 = 0; r2 < 8; ++r2)
                if (r2 < r) upd(mv[r2], mj[r2], mv[r2 + r], mj[r2 + r]);
        pkey = ((unsigned long long)__float_as_uint(mv[0]) << 32) |
               (unsigned long long)(unsigned int)(NROI - mj[0]);
    }
    s_part[t] = pkey;
    __syncthreads();

    if (t < 128) {
        unsigned long long best = s_part[t];
        #pragma unroll
        for (int r = 1; r < 8; ++r) {
            unsigned long long b2 = s_part[t + r * 128];
            if (b2 > best) best = b2;
        }
        const float maxv = __uint_as_float((unsigned int)(best >> 32));
        const int   maxj = NROI - (int)(unsigned int)(best & 0xFFFFFFFFull);

        // resolve (class, weight) for maxj by scanning the kept list
        unsigned long long lv = 0ull;
        for (int e = 0; e < G; ++e)
            if (s_idx[e] == maxj) {
                unsigned long long x = s_lvl[e];
                if (x > lv) lv = x;
            }
        const int   cls = (int)(NCLS + 1) - (int)(unsigned int)(lv & 0xFFFFFFFFull);
        const float lw  = __uint_as_float((unsigned int)(lv >> 32));

        const bool ignore = (maxv == 0.0f);
        const bool bg     = (maxv < IOU_TH) && !ignore;
        s_lab[t] = ignore ? -1 : (bg ? 0 : cls);
        s_v[t]   = maxv;
        s_w[t]   = ignore ? 0.0f : lw;
    }
    __syncthreads();

    const size_t base = (size_t)bi * 128 * (NCLS + 1);
    for (int e = t; e < 128 * (NCLS + 1); e += 1024) {
        int row = e / (NCLS + 1);
        int k   = e - row * (NCLS + 1);
        out[base + e] = (k == s_lab[row]) ? 1.0f : 0.0f;
    }
    if (t < 128) {
        out[(size_t)NROI * (NCLS + 1) + i]        = s_v[t];
        out[(size_t)NROI * (NCLS + 1) + NROI + i] = s_w[t];
    }

    // reset for next replay (wave-1 co-resident blocks already read g_cnt)
    if (bi == 0 && t == 0) g_cnt = 0;
}

extern "C" void kernel_launch(void* const* d_in, const int* in_sizes, int n_in,
                              void* d_out, int out_size) {
    const float* pc     = (const float*)d_in[0];
    const float* pd     = (const float*)d_in[1];
    // d_in[2] = rois (unused)
    const int*   labels = (const int*)d_in[3];
    const float* iou    = (const float*)d_in[4];
    float* out = (float*)d_out;

    preds_kernel<<<96, 256>>>((const float4*)pc, (const float4*)pd);
    class_nms_kernel<<<NCLS, 1024>>>(labels, iou);
    fused_final_kernel<<<NFB, 1024>>>(iou, out);
}

// round 15
// speedup vs baseline: 1.2977x; 1.1115x over previous
#include <cuda_runtime.h>
#include <cstdint>

#define NROI 6144
#define NCLS 20
#define KSEL 615            // ceil(0.1 * 6144)
#define CSORT 1024
#define IOU_TH 0.25f
#define LMAX 16384
#define GMAX 2560
#define NFB 48              // final blocks (128 ROIs each)
#define KCAP 128            // staged kept-list capacity per class

// ---- scratch (device globals; no allocations allowed) ----
__device__ float g_predsT[NCLS * NROI];
__device__ int g_list[LMAX];
__device__ unsigned long long g_lv[LMAX];    // packed (prob_bits<<32)|(NCLS-c)
__device__ int g_cnt;                        // reset by final kernel for replay

__device__ __forceinline__ void upd(float& mv, int& mj, float v, int j) {
    if (v > mv || (v == mv && j < mj)) { mv = v; mj = j; }
}

__device__ __forceinline__ unsigned long long
blockMinU64(unsigned long long v, unsigned long long* s_red, int t) {
    #pragma unroll
    for (int o = 16; o; o >>= 1) {
        unsigned long long u = __shfl_xor_sync(0xFFFFFFFFu, v, o);
        v = (u < v) ? u : v;
    }
    if ((t & 31) == 0) s_red[t >> 5] = v;
    __syncthreads();
    if (t < 32) {
        unsigned long long w = s_red[t];
        #pragma unroll
        for (int o = 16; o; o >>= 1) {
            unsigned long long u = __shfl_xor_sync(0xFFFFFFFFu, w, o);
            w = (u < w) ? u : w;
        }
        if (t == 0) s_red[0] = w;
    }
    __syncthreads();
    unsigned long long r = s_red[0];
    __syncthreads();
    return r;
}

// ============================================================
// Kernel 0: coalesced float4 transpose
// ============================================================
__global__ void __launch_bounds__(256)
preds_kernel(const float4* __restrict__ pc4, const float4* __restrict__ pd4) {
    __shared__ float sp[64 * 21];
    cudaTriggerProgrammaticLaunchCompletion();          // let class_nms ramp now
    const int b  = blockIdx.x;
    const int t  = threadIdx.x;
    const int i0 = b * 64;
    const int base4 = b * 336;

    float4* sp4 = (float4*)sp;
    #pragma unroll
    for (int r = 0; r < 2; ++r) {
        int idx = t + r * 256;
        if (idx < 336) {
            float4 a = pc4[base4 + idx];
            float4 d = pd4[base4 + idx];
            float4 o;
            o.x = a.x * d.x; o.y = a.y * d.y; o.z = a.z * d.z; o.w = a.w * d.w;
            sp4[idx] = o;
        }
    }
    __syncthreads();
    #pragma unroll
    for (int r = 0; r < 5; ++r) {
        int e = t + r * 256;
        int c = e >> 6;
        int i = e & 63;
        g_predsT[c * NROI + i0 + i] = sp[i * 21 + c + 1];
    }
}

// ============================================================
// Kernel 1: one block per class (PDL-dependent on preds).
// ============================================================
__global__ void __launch_bounds__(1024, 1)
class_nms_kernel(const int* __restrict__ labels,
                 const float* __restrict__ iou) {
    __shared__ unsigned long long cand[CSORT];
    __shared__ unsigned long long s_red[32];
    __shared__ unsigned int sh_hist[256];
    __shared__ unsigned int sh_wsum[8];
    __shared__ unsigned int sh_prefix, sh_k;
    __shared__ int sh_nc, sh_kc, sh_base;
    __shared__ int s_kidx[KCAP];
    __shared__ unsigned long long s_klv[KCAP];

    const int c = blockIdx.x;
    const int t = threadIdx.x;

    cudaTriggerProgrammaticLaunchCompletion();          // let final ramp now
    const int lab = labels[c];                          // input: safe pre-sync
    cudaGridDependencySynchronize();                    // wait for preds data

    if (lab == 0) return;

    unsigned int key[6];
    #pragma unroll
    for (int r = 0; r < 6; ++r)
        key[r] = ~__float_as_uint(g_predsT[c * NROI + r * 1024 + t]);
    if (t == 0) { sh_prefix = 0; sh_k = KSEL; }
    __syncthreads();

    // ---- 4-pass MSB radix select (exact threshold) ----
    for (int shift = 24; shift >= 0; shift -= 8) {
        if (t < 256) sh_hist[t] = 0;
        __syncthreads();
        const unsigned int prefix = sh_prefix;
        const unsigned int kcur   = sh_k;
        const unsigned int pmask  = (shift == 24) ? 0u : (0xFFFFFFFFu << (shift + 8));
        #pragma unroll
        for (int r = 0; r < 6; ++r) {
            bool active = ((key[r] & pmask) == prefix);
            unsigned int act = __ballot_sync(0xFFFFFFFFu, active);
            if (active) {
                unsigned int bin = (key[r] >> shift) & 0xFF;
                unsigned int peers = __match_any_sync(act, bin);
                if ((t & 31) == __ffs(peers) - 1)
                    atomicAdd(&sh_hist[bin], (unsigned int)__popc(peers));
            }
        }
        __syncthreads();
        unsigned int x = 0, hval = 0;
        if (t < 256) {
            hval = sh_hist[t];
            x = hval;
            #pragma unroll
            for (int off = 1; off < 32; off <<= 1) {
                unsigned int y = __shfl_up_sync(0xFFFFFFFFu, x, off);
                if ((t & 31) >= off) x += y;
            }
            if ((t & 31) == 31) sh_wsum[t >> 5] = x;
        }
        __syncthreads();
        if (t < 8) {
            unsigned int w = sh_wsum[t];
            #pragma unroll
            for (int off = 1; off < 8; off <<= 1) {
                unsigned int y = __shfl_up_sync(0xFFu, w, off);
                if (t >= off) w += y;
            }
            sh_wsum[t] = w;
        }
        __syncthreads();
        if (t < 256) {
            unsigned int incl = x + ((t >= 32) ? sh_wsum[(t >> 5) - 1] : 0u);
            unsigned int excl = incl - hval;
            if (incl >= kcur && excl < kcur) {
                sh_prefix = prefix | ((unsigned int)t << shift);
                sh_k = kcur - excl;
            }
        }
        __syncthreads();
    }
    const unsigned int thr = sh_prefix;
    const int m = (int)sh_k;

    // ---- warp-aggregated compaction (key <= thr), unsorted ----
    if (t == 0) sh_nc = 0;
    __syncthreads();
    #pragma unroll
    for (int r = 0; r < 6; ++r) {
        bool sel = (key[r] <= thr);
        unsigned int bm = __ballot_sync(0xFFFFFFFFu, sel);
        if (sel) {
            int lane = t & 31;
            int base = 0;
            if (__ffs(bm) - 1 == lane)
                base = atomicAdd(&sh_nc, __popc(bm));
            base = __shfl_sync(bm, base, __ffs(bm) - 1);
            int pos = base + __popc(bm & ((1u << lane) - 1));
            if (pos < CSORT)
                cand[pos] = ((unsigned long long)key[r] << 32) |
                            (unsigned int)(r * 1024 + t);
        }
    }
    __syncthreads();
    const int nc = sh_nc;
    if (t >= nc) cand[t] = 0xFFFFFFFFFFFFFFFFull;
    __syncthreads();

    const unsigned long long myc = cand[t];
    const unsigned int mykey = (unsigned int)(myc >> 32);
    const int myidx = (int)(unsigned int)(myc & 0xFFFFFFFFull);

    // exact participation at the threshold key (m smallest indices)
    unsigned long long tv = (t < nc && mykey == thr)
        ? (unsigned long long)(unsigned int)myidx : 0xFFFFFFFFFFFFFFFFull;
    int idx_thr = -1;
    for (int it = 0; it < m; ++it) {
        unsigned long long mn = blockMinU64(tv, s_red, t);
        idx_thr = (int)(unsigned int)mn;
        if (tv == mn) tv = 0xFFFFFFFFFFFFFFFFull;
    }
    bool alive = (t < nc) &&
                 (mykey < thr || (mykey == thr && myidx <= idx_thr));

    // ---- greedy NMS: iterated extract-min ----
    if (t == 0) sh_kc = 0;
    while (true) {
        unsigned long long v = alive ? myc : 0xFFFFFFFFFFFFFFFFull;
        unsigned long long win = blockMinU64(v, s_red, t);
        if (win == 0xFFFFFFFFFFFFFFFFull) break;
        const int oi = (int)(unsigned int)(win & 0xFFFFFFFFull);
        if (t == 0) {
            int kp = sh_kc;
            if (kp < KCAP) {
                s_kidx[kp] = oi;
                s_klv[kp] = ((unsigned long long)(~(unsigned int)(win >> 32)) << 32) |
                            (unsigned long long)(unsigned int)(NCLS - c);
            }
            sh_kc = kp + 1;
        }
        if (alive) {
            float vio = iou[(size_t)oi * NROI + myidx];
            if (vio >= IOU_TH) alive = false;
        }
    }

    __syncthreads();
    const int kcnt = min(sh_kc, KCAP);
    if (t == 0) sh_base = atomicAdd(&g_cnt, kcnt);
    __syncthreads();
    if (t < kcnt) {
        g_list[sh_base + t] = s_kidx[t];
        g_lv[sh_base + t]   = s_klv[t];
    }
}

// ============================================================
// Kernel 2: fused partial-max + list-scan resolution
// (PDL-dependent on class_nms).
// ============================================================
__global__ void __launch_bounds__(1024, 1)
fused_final_kernel(const float* __restrict__ iou, float* __restrict__ out) {
    __shared__ int s_idx[GMAX];
    __shared__ unsigned long long s_lvl[GMAX];
    __shared__ unsigned long long s_part[1024];
    __shared__ int   s_lab[128];
    __shared__ float s_v[128];
    __shared__ float s_w[128];

    const int t  = threadIdx.x;
    const int bi = blockIdx.x;
    const int il = t & 127;
    const int ch = t >> 7;
    const int i  = bi * 128 + il;

    cudaGridDependencySynchronize();                    // wait for class lists

    const int G = min(g_cnt, GMAX);

    for (int e = t; e < G; e += 1024) {
        s_idx[e] = g_list[e];
        s_lvl[e] = g_lv[e];
    }
    __syncthreads();

    const int len = (G + 7) >> 3;
    const int g0 = ch * len;
    const int g1 = min(G, g0 + len);

    unsigned long long pkey = 0ull;
    if (g0 < g1) {
        float mv[8]; int mj[8];
        #pragma unroll
        for (int r = 0; r < 8; ++r) { mv[r] = -1.0f; mj[r] = 0; }
        int g = g0;
        for (; g + 8 <= g1; g += 8) {
            #pragma unroll
            for (int r = 0; r < 8; ++r) {
                int j = s_idx[g + r];
                upd(mv[r], mj[r], iou[(size_t)j * NROI + i], j);
            }
        }
        #pragma unroll 8
        for (; g < g1; ++g) {
            int j = s_idx[g];
            upd(mv[0], mj[0], iou[(size_t)j * NROI + i], j);
        }
        #pragma unroll
        for (int r = 4; r >= 1; r >>= 1)
            #pragma unroll
            for (int r2 = 0; r2 < 8; ++r2)
                if (r2 < r) upd(mv[r2], mj[r2], mv[r2 + r], mj[r2 + r]);
        pkey = ((unsigned long long)__float_as_uint(mv[0]) << 32) |
               (unsigned long long)(unsigned int)(NROI - mj[0]);
    }
    s_part[t] = pkey;
    __syncthreads();

    if (t < 128) {
        unsigned long long best = s_part[t];
        #pragma unroll
        for (int r = 1; r < 8; ++r) {
            unsigned long long b2 = s_part[t + r * 128];
            if (b2 > best) best = b2;
        }
        const float maxv = __uint_as_float((unsigned int)(best >> 32));
        const int   maxj = NROI - (int)(unsigned int)(best & 0xFFFFFFFFull);

        unsigned long long lv = 0ull;
        for (int e = 0; e < G; ++e)
            if (s_idx[e] == maxj) {
                unsigned long long x = s_lvl[e];
                if (x > lv) lv = x;
            }
        const int   cls = (int)(NCLS + 1) - (int)(unsigned int)(lv & 0xFFFFFFFFull);
        const float lw  = __uint_as_float((unsigned int)(lv >> 32));

        const bool ignore = (maxv == 0.0f);
        const bool bg     = (maxv < IOU_TH) && !ignore;
        s_lab[t] = ignore ? -1 : (bg ? 0 : cls);
        s_v[t]   = maxv;
        s_w[t]   = ignore ? 0.0f : lw;
    }
    __syncthreads();

    const size_t base = (size_t)bi * 128 * (NCLS + 1);
    for (int e = t; e < 128 * (NCLS + 1); e += 1024) {
        int row = e / (NCLS + 1);
        int k   = e - row * (NCLS + 1);
        out[base + e] = (k == s_lab[row]) ? 1.0f : 0.0f;
    }
    if (t < 128) {
        out[(size_t)NROI * (NCLS + 1) + i]        = s_v[t];
        out[(size_t)NROI * (NCLS + 1) + NROI + i] = s_w[t];
    }

    if (bi == 0 && t == 0) g_cnt = 0;
}

extern "C" void kernel_launch(void* const* d_in, const int* in_sizes, int n_in,
                              void* d_out, int out_size) {
    const float* pc     = (const float*)d_in[0];
    const float* pd     = (const float*)d_in[1];
    // d_in[2] = rois (unused)
    const int*   labels = (const int*)d_in[3];
    const float* iou    = (const float*)d_in[4];
    float* out = (float*)d_out;

    // kernel 0: plain launch
    preds_kernel<<<96, 256>>>((const float4*)pc, (const float4*)pd);

    // kernel 1: PDL-dependent on preds
    {
        cudaLaunchConfig_t cfg = {};
        cfg.gridDim  = dim3(NCLS, 1, 1);
        cfg.blockDim = dim3(1024, 1, 1);
        cudaLaunchAttribute attr[1];
        attr[0].id = cudaLaunchAttributeProgrammaticStreamSerialization;
        attr[0].val.programmaticStreamSerializationAllowed = 1;
        cfg.attrs = attr;
        cfg.numAttrs = 1;
        cudaLaunchKernelEx(&cfg, class_nms_kernel, labels, iou);
    }

    // kernel 2: PDL-dependent on class_nms
    {
        cudaLaunchConfig_t cfg = {};
        cfg.gridDim  = dim3(NFB, 1, 1);
        cfg.blockDim = dim3(1024, 1, 1);
        cudaLaunchAttribute attr[1];
        attr[0].id = cudaLaunchAttributeProgrammaticStreamSerialization;
        attr[0].val.programmaticStreamSerializationAllowed = 1;
        cfg.attrs = attr;
        cfg.numAttrs = 1;
        cudaLaunchKernelEx(&cfg, fused_final_kernel, iou, out);
    }
}